// round 15
// baseline (speedup 1.0000x reference)
#include <cuda_runtime.h>
#include <cuda_fp16.h>
#include <math.h>
#include <stdint.h>

// Problem constants (confirmed: inner = DIM_HEAD*dim = 16384)
#define BATCH   2
#define NTOK    2048
#define DIM     256
#define HEADS   8
#define INNER   16384
#define DHEAD   2048
#define TOK     (BATCH*NTOK)      // 4096
#define ATT_SCALE 0.125f
#define LN_EPS  1e-5f
#define NSPLIT  8
#define KS      (DHEAD/NSPLIT)    // 256
#define NTILES  (NTOK/128)        // 16 column tiles per head block
#define NROWS   (BATCH*HEADS*NTOK) // 32768 attention rows

// ---------------- scratch ---------------------------------------------------
__device__ float g_xn[TOK * DIM];
__device__ float g_pm[(size_t)HEADS * NSPLIT * DIM * DIM];
__device__ float g_pg[(size_t)HEADS * NSPLIT * DIM * DIM];
__device__ float g_op[(size_t)BATCH * HEADS * NTOK * DIM];
__device__ float g_sp[(size_t)NROWS * NTILES];   // row-sum partials
__device__ float g_ri[NROWS];                    // 1/rowsum

__device__ __half g_xnh[TOK * DIM];
__device__ __half g_mth[HEADS * DIM * DIM];
__device__ __half g_ghh[HEADS * DIM * DIM];
__device__ __half g_th [(size_t)BATCH * HEADS * NTOK * DIM];
__device__ __half g_uth[(size_t)BATCH * HEADS * DIM * NTOK];
__device__ __half g_eh [(size_t)BATCH * NTOK * INNER];

// ---------------- asm helpers ------------------------------------------------
__device__ __forceinline__ uint32_t smem_u32(const void* p) {
    uint32_t a;
    asm("{ .reg .u64 tmp; cvta.to.shared.u64 tmp, %1; cvt.u32.u64 %0, tmp; }"
        : "=r"(a) : "l"(p));
    return a;
}
__device__ __forceinline__ void ldsm4u(uint32_t* d, uint32_t a)
{
    asm volatile("ldmatrix.sync.aligned.m8n8.x4.shared.b16 {%0,%1,%2,%3}, [%4];"
                 : "=r"(d[0]), "=r"(d[1]), "=r"(d[2]), "=r"(d[3]) : "r"(a));
}
__device__ __forceinline__ void mma_fp16(float* d, const uint32_t* a, const uint32_t* b)
{
    asm volatile(
        "mma.sync.aligned.m16n8k16.row.col.f32.f16.f16.f32 "
        "{%0,%1,%2,%3}, {%4,%5,%6,%7}, {%8,%9}, {%0,%1,%2,%3};"
        : "+f"(d[0]), "+f"(d[1]), "+f"(d[2]), "+f"(d[3])
        : "r"(a[0]), "r"(a[1]), "r"(a[2]), "r"(a[3]), "r"(b[0]), "r"(b[1]));
}
#define CP16(dst, src) \
    asm volatile("cp.async.cg.shared.global [%0], [%1], 16;" :: "r"(dst), "l"(src))
#define CP_COMMIT() asm volatile("cp.async.commit_group;" ::: "memory")
#define CP_WAIT0()  asm volatile("cp.async.wait_group 0;" ::: "memory")

// stage layout: 2 tiles of 128 rows x 64 fp16, row stride 144 B (128 + 16 pad)
// 144/16 = 9 (odd) -> ldmatrix rows hit distinct 16B banks: conflict-free.
#define LDR     144
#define OFF_A   0
#define OFF_B   18432              // 128*144
#define STAGE   36864              // 2 tiles
#define MM_SMEM (2 * STAGE)        // 72 KB, 2 CTAs/SM -> 144 KB

// mma_nt output modes
#define OUT_F32   0   // C = alpha * acc                (fp32)
#define OUT_F16   1   // Chi = fp16(alpha * acc)
#define OUT_EXP   2   // Chi = fp16(exp(alpha*acc)), + row-sum partials
#define OUT_DIV   3   // C = rinv[row] * acc            (fp32)

// ---------------- fp16 tensor-core GEMM (NT), k-chunk 64, 2-stage -----------
// acc[m][n] = sum_k A[m][k]*B[n][k]   (both fp16, fp32 accum)
// Block 128x128, 8 warps of 32x64. Requires K % 64 == 0.
template<int MODE>
__global__ void __launch_bounds__(256, 2)
mma_nt(const __half* __restrict__ A, const __half* __restrict__ B,
       float* __restrict__ C, __half* __restrict__ Chi,
       float* __restrict__ Part, const float* __restrict__ Rinv,
       int K, int lda, int ldb, int ldc,
       int hdiv,
       long long sAb, long long sAh,
       long long sBb, long long sBh,
       long long sCb, long long sCh,
       float alpha)
{
    extern __shared__ __align__(16) char smem[];
    __shared__ float ssum[128][2];
    uint32_t sb = smem_u32(smem);

    int bz = blockIdx.z;
    int zb = bz / hdiv, zh = bz % hdiv;
    const __half* Ab = A + (long long)zb * sAb + (long long)zh * sAh;
    const __half* Bb = B + (long long)zb * sBb + (long long)zh * sBh;
    long long coff = (long long)zb * sCb + (long long)zh * sCh;

    int m0 = blockIdx.y * 128;
    int n0 = blockIdx.x * 128;
    int tid  = threadIdx.x;
    int warp = tid >> 5;
    int lane = tid & 31;
    int wm = (warp & 3) * 32;
    int wn = (warp >> 2) * 64;

    // loader: 2 threads per row; each does 4 x 16B per tile
    int lrow = tid >> 1;                 // 0..127
    int lcol = (tid & 1) * 32;           // element offset (32 fp16 = 64 B)
    uint32_t lso = (uint32_t)lrow * LDR + (uint32_t)(tid & 1) * 64;

    float acc[2][8][4];
    #pragma unroll
    for (int i = 0; i < 2; i++)
        #pragma unroll
        for (int j = 0; j < 8; j++)
            #pragma unroll
            for (int c = 0; c < 4; c++) acc[i][j][c] = 0.f;

    const int NC = K / 64;

    auto load_stage = [&](int st, int k0) {
        uint32_t s0 = sb + (uint32_t)st * STAGE;
        const __half* pa = Ab + (long long)(m0 + lrow) * lda + k0 + lcol;
        const __half* pb = Bb + (long long)(n0 + lrow) * ldb + k0 + lcol;
        #pragma unroll
        for (int i = 0; i < 4; i++) {
            CP16(s0 + OFF_A + lso + i * 16, pa + i * 8);
            CP16(s0 + OFF_B + lso + i * 16, pb + i * 8);
        }
    };

    load_stage(0, 0);
    CP_COMMIT();

    for (int i = 0; i < NC; i++) {
        CP_WAIT0();
        __syncthreads();          // proves compute(i-1) done -> buffer (i+1)&1 reusable
        if (i + 1 < NC) { load_stage((i + 1) & 1, (i + 1) * 64); CP_COMMIT(); }

        uint32_t base = sb + (uint32_t)(i & 1) * STAGE;

        #pragma unroll
        for (int s = 0; s < 64; s += 16) {
            uint32_t ah[2][4];
            #pragma unroll
            for (int ii = 0; ii < 2; ii++) {
                uint32_t ra = base + (uint32_t)(wm + ii * 16 + (lane & 15)) * LDR
                            + (uint32_t)(s + ((lane >> 4) << 3)) * 2;
                ldsm4u(ah[ii], ra + OFF_A);
            }
            #pragma unroll
            for (int j = 0; j < 4; j++) {
                uint32_t rb = base + (uint32_t)(wn + j * 16 + ((lane >> 4) << 3) + (lane & 7)) * LDR
                            + (uint32_t)(s + ((lane >> 3) & 1) * 8) * 2;
                uint32_t bh[4];
                ldsm4u(bh, rb + OFF_B);
                #pragma unroll
                for (int jj = 0; jj < 2; jj++)
                    #pragma unroll
                    for (int ii = 0; ii < 2; ii++)
                        mma_fp16(acc[ii][j * 2 + jj], ah[ii], bh + jj * 2);
            }
        }
    }

    // ---------------- epilogue ----------------
    float rowacc[2][2] = {{0.f, 0.f}, {0.f, 0.f}};
    float rv[2][2];
    if (MODE == OUT_DIV) {
        #pragma unroll
        for (int i = 0; i < 2; i++)
            #pragma unroll
            for (int hh = 0; hh < 2; hh++)
                rv[i][hh] = Rinv[(long long)bz * NTOK + m0 + wm + i * 16 + hh * 8 + (lane >> 2)];
    }

    #pragma unroll
    for (int i = 0; i < 2; i++) {
        #pragma unroll
        for (int j = 0; j < 8; j++) {
            int row = m0 + wm + i * 16 + (lane >> 2);
            int col = n0 + wn + j * 8 + (lane & 3) * 2;
            #pragma unroll
            for (int hh = 0; hh < 2; hh++) {
                long long off = coff + (long long)(row + hh * 8) * ldc + col;
                float v0 = acc[i][j][hh * 2 + 0];
                float v1 = acc[i][j][hh * 2 + 1];
                if (MODE == OUT_F32) {
                    float2 v = { alpha * v0, alpha * v1 };
                    *(float2*)(C + off) = v;
                } else if (MODE == OUT_F16) {
                    *(__half2*)(Chi + off) =
                        __halves2half2(__float2half(alpha * v0), __float2half(alpha * v1));
                } else if (MODE == OUT_EXP) {
                    float e0 = __expf(alpha * v0);
                    float e1 = __expf(alpha * v1);
                    *(__half2*)(Chi + off) =
                        __halves2half2(__float2half(e0), __float2half(e1));
                    rowacc[i][hh] += e0 + e1;
                } else { // OUT_DIV
                    float2 v = { rv[i][hh] * v0, rv[i][hh] * v1 };
                    *(float2*)(C + off) = v;
                }
            }
        }
    }

    if (MODE == OUT_EXP) {
        #pragma unroll
        for (int i = 0; i < 2; i++)
            #pragma unroll
            for (int hh = 0; hh < 2; hh++) {
                rowacc[i][hh] += __shfl_xor_sync(0xffffffffu, rowacc[i][hh], 1);
                rowacc[i][hh] += __shfl_xor_sync(0xffffffffu, rowacc[i][hh], 2);
            }
        if ((lane & 3) == 0) {
            #pragma unroll
            for (int i = 0; i < 2; i++)
                #pragma unroll
                for (int hh = 0; hh < 2; hh++)
                    ssum[wm + i * 16 + hh * 8 + (lane >> 2)][warp >> 2] = rowacc[i][hh];
        }
        __syncthreads();
        if (tid < 128) {
            float sp = ssum[tid][0] + ssum[tid][1];
            Part[((long long)bz * NTOK + m0 + tid) * NTILES + blockIdx.x] = sp;
        }
    }
}

// ---------------- rowsum -> reciprocal ---------------------------------------
__global__ void rowsum_kernel(const float* __restrict__ part, float* __restrict__ rinv)
{
    int idx = blockIdx.x * 256 + threadIdx.x;
    const float* p = part + (long long)idx * NTILES;
    float s = 0.f;
    #pragma unroll
    for (int i = 0; i < NTILES; i++) s += p[i];
    rinv[idx] = 1.0f / s;
}

// ---------------- LayerNorm (+fp16 quantize) ---------------------------------
__global__ void ln_kernel(const float* __restrict__ x,
                          const float* __restrict__ gamma,
                          float* __restrict__ xn,
                          __half* __restrict__ xnh)
{
    int row = blockIdx.x;
    int t   = threadIdx.x;
    float v = x[row * DIM + t];

    __shared__ float s1[8], s2[8];
    float a = v, b = v * v;
    #pragma unroll
    for (int o = 16; o > 0; o >>= 1) {
        a += __shfl_xor_sync(0xffffffffu, a, o);
        b += __shfl_xor_sync(0xffffffffu, b, o);
    }
    int lane = t & 31, w = t >> 5;
    if (lane == 0) { s1[w] = a; s2[w] = b; }
    __syncthreads();
    if (t == 0) {
        float sa = 0.f, sb = 0.f;
        #pragma unroll
        for (int i = 0; i < 8; i++) { sa += s1[i]; sb += s2[i]; }
        s1[0] = sa * (1.0f / DIM);
        s2[0] = sb * (1.0f / DIM);
    }
    __syncthreads();
    float mu  = s1[0];
    float var = s2[0] - mu * mu;
    float rr  = rsqrtf(var + LN_EPS);
    float o = (v - mu) * rr * (gamma[t] + 1.0f);
    xn [row * DIM + t] = o;
    xnh[row * DIM + t] = __float2half(o);
}

// ---------------- combined split-K 64x64 precompute GEMM --------------------
// z in [0, HEADS*NSPLIT)          : Mt partial = Wk_h^T * Wq_h     (TN)
// z in [HEADS*NSPLIT, 2*H*NSPLIT) : G  partial = Wo_h  * Wv_h      (NN)
__global__ void __launch_bounds__(256)
gemm64_pre(const float* __restrict__ Wk, const float* __restrict__ Wq,
           const float* __restrict__ Wo, const float* __restrict__ Wv,
           float* __restrict__ pm, float* __restrict__ pg)
{
    __shared__ float As[16][68];
    __shared__ float Bs[16][68];

    int z = blockIdx.z;
    bool isG = z >= HEADS * NSPLIT;
    int zz = isG ? z - HEADS * NSPLIT : z;
    int h = zz / NSPLIT, sp = zz % NSPLIT;
    long long hk0 = (long long)h * DHEAD + (long long)sp * KS;

    const float* Ab = isG ? (Wo + hk0) : (Wk + hk0 * DIM);
    const float* Bb = (isG ? Wv : Wq) + hk0 * DIM;
    int lda = isG ? INNER : DIM;
    float* Cb = (isG ? pg : pm) + (long long)zz * DIM * DIM;

    int m0 = blockIdx.y * 64;
    int n0 = blockIdx.x * 64;
    int tid = threadIdx.x;
    int tx = tid & 15;
    int ty = tid >> 4;

    float acc[4][4];
    #pragma unroll
    for (int i = 0; i < 4; i++)
        #pragma unroll
        for (int j = 0; j < 4; j++) acc[i][j] = 0.f;

    for (int k0 = 0; k0 < KS; k0 += 16) {
        if (!isG) {
            int kk  = tid >> 4;
            int mm4 = (tid & 15) << 2;
            float4 a = *(const float4*)(Ab + (long long)(k0 + kk) * lda + m0 + mm4);
            *(float4*)&As[kk][mm4] = a;
        } else {
            int mm = tid >> 2;
            int kq = (tid & 3) << 2;
            float4 a = *(const float4*)(Ab + (long long)(m0 + mm) * lda + k0 + kq);
            As[kq + 0][mm] = a.x;
            As[kq + 1][mm] = a.y;
            As[kq + 2][mm] = a.z;
            As[kq + 3][mm] = a.w;
        }
        {
            int kk  = tid >> 4;
            int nn4 = (tid & 15) << 2;
            float4 b = *(const float4*)(Bb + (long long)(k0 + kk) * DIM + n0 + nn4);
            *(float4*)&Bs[kk][nn4] = b;
        }
        __syncthreads();

        #pragma unroll
        for (int kk = 0; kk < 16; kk++) {
            float4 ra = *(const float4*)&As[kk][ty * 4];
            float4 rb = *(const float4*)&Bs[kk][tx * 4];
            float va[4] = { ra.x, ra.y, ra.z, ra.w };
            float vb[4] = { rb.x, rb.y, rb.z, rb.w };
            #pragma unroll
            for (int i = 0; i < 4; i++)
                #pragma unroll
                for (int j = 0; j < 4; j++)
                    acc[i][j] = fmaf(va[i], vb[j], acc[i][j]);
        }
        __syncthreads();
    }

    #pragma unroll
    for (int i = 0; i < 4; i++)
        #pragma unroll
        for (int j = 0; j < 4; j++)
            Cb[(long long)(m0 + ty * 4 + i) * DIM + (n0 + tx * 4 + j)] = acc[i][j];
}

// ------------- reduce split-K partials (both Mt and G) -> fp16 --------------
__global__ void reduce_pre_kernel(const float* __restrict__ pm,
                                  const float* __restrict__ pg,
                                  __half* __restrict__ mth,
                                  __half* __restrict__ ghh)
{
    int gi = blockIdx.x * 256 + threadIdx.x;          // over 2*HEADS*DIM*DIM
    bool isG = gi >= HEADS * DIM * DIM;
    int idx = isG ? gi - HEADS * DIM * DIM : gi;
    int h   = idx >> 16;
    int off = idx & 65535;
    const float* p = (isG ? pg : pm) + (long long)h * NSPLIT * 65536 + off;
    float acc = 0.f;
    #pragma unroll
    for (int s = 0; s < NSPLIT; s++) acc += p[(long long)s * 65536];
    (isG ? ghh : mth)[idx] = __float2half(acc);
}

// ---------------- reduce per-head partials ----------------------------------
__global__ void reduce_kernel(const float* __restrict__ op, float* __restrict__ out)
{
    int row = blockIdx.x;
    int t   = threadIdx.x;
    int b   = row >> 11;
    int q   = row & 2047;
    const float* base = op + (((long long)b * HEADS) * NTOK + q) * DIM + t;
    float acc = 0.f;
    #pragma unroll
    for (int h = 0; h < HEADS; h++)
        acc += base[(long long)h * NTOK * DIM];
    out[(long long)row * DIM + t] = acc;
}

// ---------------- launch ----------------------------------------------------
extern "C" void kernel_launch(void* const* d_in, const int* in_sizes, int n_in,
                              void* d_out, int out_size)
{
    const float* x     = (const float*)d_in[0];
    const float* gamma = (const float*)d_in[1];
    const float* Wq    = (const float*)d_in[2];
    const float* Wk    = (const float*)d_in[3];
    const float* Wv    = (const float*)d_in[4];
    const float* Wo    = (const float*)d_in[5];
    float* out = (float*)d_out;

    cudaFuncSetAttribute(mma_nt<OUT_F32>, cudaFuncAttributeMaxDynamicSharedMemorySize, MM_SMEM);
    cudaFuncSetAttribute(mma_nt<OUT_F16>, cudaFuncAttributeMaxDynamicSharedMemorySize, MM_SMEM);
    cudaFuncSetAttribute(mma_nt<OUT_EXP>, cudaFuncAttributeMaxDynamicSharedMemorySize, MM_SMEM);
    cudaFuncSetAttribute(mma_nt<OUT_DIV>, cudaFuncAttributeMaxDynamicSharedMemorySize, MM_SMEM);

    float *xn, *pm, *pg, *op, *sp, *ri;
    __half *xnh, *mth, *ghh, *th, *uth, *eh;
    cudaGetSymbolAddress((void**)&xn,  g_xn);
    cudaGetSymbolAddress((void**)&pm,  g_pm);
    cudaGetSymbolAddress((void**)&pg,  g_pg);
    cudaGetSymbolAddress((void**)&op,  g_op);
    cudaGetSymbolAddress((void**)&sp,  g_sp);
    cudaGetSymbolAddress((void**)&ri,  g_ri);
    cudaGetSymbolAddress((void**)&xnh, g_xnh);
    cudaGetSymbolAddress((void**)&mth, g_mth);
    cudaGetSymbolAddress((void**)&ghh, g_ghh);
    cudaGetSymbolAddress((void**)&th,  g_th);
    cudaGetSymbolAddress((void**)&uth, g_uth);
    cudaGetSymbolAddress((void**)&eh,  g_eh);

    const long long TD  = (long long)NTOK * DIM;
    const long long HTD = (long long)HEADS * TD;
    const long long SB  = (long long)NTOK * INNER;
    const long long DD  = (long long)DIM * DIM;

    // 1) LayerNorm (+fp16 quantize fused)
    ln_kernel<<<TOK, 256>>>(x, gamma, xn, xnh);

    // 2) combined precomputes: Mt_h = Wk_h^T Wq_h ; G_h = Wo_h Wv_h
    {
        dim3 grid(4, 4, 2 * HEADS * NSPLIT);
        gemm64_pre<<<grid, 256>>>(Wk, Wq, Wo, Wv, pm, pg);
        reduce_pre_kernel<<<2 * HEADS * DIM * DIM / 256, 256>>>(pm, pg, mth, ghh);
    }

    // 3) T[b][h] = xn_b * Mt_h^T
    {
        dim3 grid(DIM / 128, NTOK / 128, BATCH * HEADS);
        mma_nt<OUT_F16><<<grid, 256, MM_SMEM>>>(
            xnh, mth, nullptr, th, nullptr, nullptr,
            DIM, DIM, DIM, DIM, HEADS,
            TD, 0, 0, DD, HTD, TD, 1.0f);
    }

    // 4) E = exp(scale * T * xn^T)  (+ row-sum partials)
    {
        dim3 grid(NTOK / 128, NTOK / 128, BATCH * HEADS);
        mma_nt<OUT_EXP><<<grid, 256, MM_SMEM>>>(
            th, xnh, nullptr, eh, sp, nullptr,
            DIM, DIM, DIM, INNER, HEADS,
            HTD, TD, TD, 0, SB, (long long)DHEAD,
            ATT_SCALE);
    }

    // 5) rinv = 1 / rowsum
    rowsum_kernel<<<NROWS / 256, 256>>>(sp, ri);

    // 6) Ut[b][h] = G_h * xn_b^T
    {
        dim3 grid(NTOK / 128, DIM / 128, BATCH * HEADS);
        mma_nt<OUT_F16><<<grid, 256, MM_SMEM>>>(
            ghh, xnh, nullptr, uth, nullptr, nullptr,
            DIM, DIM, DIM, NTOK, HEADS,
            0, DD, TD, 0, HTD, TD, 1.0f);
    }

    // 7) op[b][h] = (E[b][h] * Ut[b][h]^T) * rinv
    {
        dim3 grid(DIM / 128, NTOK / 128, BATCH * HEADS);
        mma_nt<OUT_DIV><<<grid, 256, MM_SMEM>>>(
            eh, uth, op, nullptr, nullptr, ri,
            NTOK, INNER, NTOK, DIM, HEADS,
            SB, (long long)DHEAD, HTD, TD, HTD, TD,
            1.0f);
    }

    // 8) out = sum_h op[b][h]
    reduce_kernel<<<TOK, 256>>>(op, out);
}

// round 16
// speedup vs baseline: 1.0576x; 1.0576x over previous
#include <cuda_runtime.h>
#include <cuda_fp16.h>
#include <math.h>
#include <stdint.h>

// Problem constants (confirmed: inner = DIM_HEAD*dim = 16384)
#define BATCH   2
#define NTOK    2048
#define DIM     256
#define HEADS   8
#define INNER   16384
#define DHEAD   2048
#define TOK     (BATCH*NTOK)      // 4096
#define ATT_SCALE 0.125f
#define LN_EPS  1e-5f
#define NSPLIT  8
#define KS      (DHEAD/NSPLIT)    // 256
#define NTILES  (NTOK/64)         // 32 column tiles per head block (block N = 64)
#define NROWS   (BATCH*HEADS*NTOK) // 32768 attention rows

// ---------------- scratch ---------------------------------------------------
__device__ float g_xn[TOK * DIM];
__device__ float g_pm[(size_t)HEADS * NSPLIT * DIM * DIM];
__device__ float g_pg[(size_t)HEADS * NSPLIT * DIM * DIM];
__device__ float g_op[(size_t)BATCH * HEADS * NTOK * DIM];
__device__ float g_sp[(size_t)NROWS * NTILES];   // row-sum partials
__device__ float g_ri[NROWS];                    // 1/rowsum

__device__ __half g_xnh[TOK * DIM];
__device__ __half g_mth[HEADS * DIM * DIM];
__device__ __half g_ghh[HEADS * DIM * DIM];
__device__ __half g_th [(size_t)BATCH * HEADS * NTOK * DIM];
__device__ __half g_uth[(size_t)BATCH * HEADS * DIM * NTOK];
__device__ __half g_eh [(size_t)BATCH * NTOK * INNER];

// ---------------- asm helpers ------------------------------------------------
__device__ __forceinline__ uint32_t smem_u32(const void* p) {
    uint32_t a;
    asm("{ .reg .u64 tmp; cvta.to.shared.u64 tmp, %1; cvt.u32.u64 %0, tmp; }"
        : "=r"(a) : "l"(p));
    return a;
}
__device__ __forceinline__ void ldsm4u(uint32_t* d, uint32_t a)
{
    asm volatile("ldmatrix.sync.aligned.m8n8.x4.shared.b16 {%0,%1,%2,%3}, [%4];"
                 : "=r"(d[0]), "=r"(d[1]), "=r"(d[2]), "=r"(d[3]) : "r"(a));
}
__device__ __forceinline__ void mma_fp16(float* d, const uint32_t* a, const uint32_t* b)
{
    asm volatile(
        "mma.sync.aligned.m16n8k16.row.col.f32.f16.f16.f32 "
        "{%0,%1,%2,%3}, {%4,%5,%6,%7}, {%8,%9}, {%0,%1,%2,%3};"
        : "+f"(d[0]), "+f"(d[1]), "+f"(d[2]), "+f"(d[3])
        : "r"(a[0]), "r"(a[1]), "r"(a[2]), "r"(a[3]), "r"(b[0]), "r"(b[1]));
}
#define CP16(dst, src) \
    asm volatile("cp.async.cg.shared.global [%0], [%1], 16;" :: "r"(dst), "l"(src))
#define CP_COMMIT() asm volatile("cp.async.commit_group;" ::: "memory")
#define CP_WAIT0()  asm volatile("cp.async.wait_group 0;" ::: "memory")

// stage layout: A tile 128 rows x 32 fp16 (80B stride), B tile 64 rows x 32 fp16
#define OFF_A   0
#define OFF_B   10240              // 128*80
#define STAGE   15360              // + 64*80
#define MM_SMEM (2 * STAGE)        // 30720 B; 3 CTAs/SM -> 90 KB

// mma_nt output modes
#define OUT_F32   0   // C = alpha * acc                (fp32)
#define OUT_F16   1   // Chi = fp16(alpha * acc)
#define OUT_EXP   2   // Chi = fp16(exp(alpha*acc)), + row-sum partials
#define OUT_DIV   3   // C = rinv[row] * acc            (fp32)

// ---------------- fp16 tensor-core GEMM (NT), k32 chunks, 2-stage -----------
// acc[m][n] = sum_k A[m][k]*B[n][k]   (both fp16, fp32 accum)
// Block 128x64, 8 warps of 32x32 (4m x 2n). Requires K % 32 == 0, N % 64 == 0.
template<int MODE>
__global__ void __launch_bounds__(256, 3)
mma_nt(const __half* __restrict__ A, const __half* __restrict__ B,
       float* __restrict__ C, __half* __restrict__ Chi,
       float* __restrict__ Part, const float* __restrict__ Rinv,
       int K, int lda, int ldb, int ldc,
       int hdiv,
       long long sAb, long long sAh,
       long long sBb, long long sBh,
       long long sCb, long long sCh,
       float alpha)
{
    extern __shared__ __align__(16) char smem[];
    __shared__ float ssum[128][2];
    uint32_t sb = smem_u32(smem);

    int bz = blockIdx.z;
    int zb = bz / hdiv, zh = bz % hdiv;
    const __half* Ab = A + (long long)zb * sAb + (long long)zh * sAh;
    const __half* Bb = B + (long long)zb * sBb + (long long)zh * sBh;
    long long coff = (long long)zb * sCb + (long long)zh * sCh;

    int m0 = blockIdx.y * 128;
    int n0 = blockIdx.x * 64;
    int tid  = threadIdx.x;
    int warp = tid >> 5;
    int lane = tid & 31;
    int wm = (warp & 3) * 32;      // 4 m-warps
    int wn = (warp >> 2) * 32;     // 2 n-warps

    // loader: A = 512 16B-chunks (2/thread), B = 256 (1/thread)
    int a0r = tid >> 1, a0q = tid & 1;              // chunks 0..511: row=c>>2,q=c&3
    // simpler: chunk ids tid and tid+256
    int ca0 = tid, ca1 = tid + 256;
    int ra0 = ca0 >> 2, qa0 = ca0 & 3;
    int ra1 = ca1 >> 2, qa1 = ca1 & 3;
    int rb_ = tid >> 2, qb_ = tid & 3;
    (void)a0r; (void)a0q;

    float acc[2][4][4];
    #pragma unroll
    for (int i = 0; i < 2; i++)
        #pragma unroll
        for (int j = 0; j < 4; j++)
            #pragma unroll
            for (int c = 0; c < 4; c++) acc[i][j][c] = 0.f;

    const int NC = K / 32;

    auto load_stage = [&](int st, int k0) {
        uint32_t s0 = sb + (uint32_t)st * STAGE;
        CP16(s0 + OFF_A + (uint32_t)ra0 * 80 + qa0 * 16,
             Ab + (long long)(m0 + ra0) * lda + k0 + qa0 * 8);
        CP16(s0 + OFF_A + (uint32_t)ra1 * 80 + qa1 * 16,
             Ab + (long long)(m0 + ra1) * lda + k0 + qa1 * 8);
        CP16(s0 + OFF_B + (uint32_t)rb_ * 80 + qb_ * 16,
             Bb + (long long)(n0 + rb_) * ldb + k0 + qb_ * 8);
    };

    load_stage(0, 0);
    CP_COMMIT();

    for (int i = 0; i < NC; i++) {
        CP_WAIT0();
        __syncthreads();          // proves compute(i-1) done -> buffer (i+1)&1 reusable
        if (i + 1 < NC) { load_stage((i + 1) & 1, (i + 1) * 32); CP_COMMIT(); }

        uint32_t base = sb + (uint32_t)(i & 1) * STAGE;

        #pragma unroll
        for (int s = 0; s < 32; s += 16) {
            uint32_t ah[2][4];
            #pragma unroll
            for (int ii = 0; ii < 2; ii++) {
                uint32_t ra = base + OFF_A
                            + (uint32_t)(wm + ii * 16 + (lane & 15)) * 80
                            + (uint32_t)(s + ((lane >> 4) << 3)) * 2;
                ldsm4u(ah[ii], ra);
            }
            #pragma unroll
            for (int t = 0; t < 2; t++) {
                uint32_t rb = base + OFF_B
                            + (uint32_t)(wn + t * 16 + ((lane >> 4) << 3) + (lane & 7)) * 80
                            + (uint32_t)(s + ((lane >> 3) & 1) * 8) * 2;
                uint32_t bh[4];
                ldsm4u(bh, rb);
                #pragma unroll
                for (int jj = 0; jj < 2; jj++)
                    #pragma unroll
                    for (int ii = 0; ii < 2; ii++)
                        mma_fp16(acc[ii][t * 2 + jj], ah[ii], bh + jj * 2);
            }
        }
    }

    // ---------------- epilogue ----------------
    float rowacc[2][2] = {{0.f, 0.f}, {0.f, 0.f}};
    float rv[2][2];
    if (MODE == OUT_DIV) {
        #pragma unroll
        for (int i = 0; i < 2; i++)
            #pragma unroll
            for (int hh = 0; hh < 2; hh++)
                rv[i][hh] = Rinv[(long long)bz * NTOK + m0 + wm + i * 16 + hh * 8 + (lane >> 2)];
    }

    #pragma unroll
    for (int i = 0; i < 2; i++) {
        #pragma unroll
        for (int j = 0; j < 4; j++) {
            int row = m0 + wm + i * 16 + (lane >> 2);
            int col = n0 + wn + j * 8 + (lane & 3) * 2;
            #pragma unroll
            for (int hh = 0; hh < 2; hh++) {
                long long off = coff + (long long)(row + hh * 8) * ldc + col;
                float v0 = acc[i][j][hh * 2 + 0];
                float v1 = acc[i][j][hh * 2 + 1];
                if (MODE == OUT_F32) {
                    float2 v = { alpha * v0, alpha * v1 };
                    *(float2*)(C + off) = v;
                } else if (MODE == OUT_F16) {
                    *(__half2*)(Chi + off) =
                        __halves2half2(__float2half(alpha * v0), __float2half(alpha * v1));
                } else if (MODE == OUT_EXP) {
                    float e0 = __expf(alpha * v0);
                    float e1 = __expf(alpha * v1);
                    *(__half2*)(Chi + off) =
                        __halves2half2(__float2half(e0), __float2half(e1));
                    rowacc[i][hh] += e0 + e1;
                } else { // OUT_DIV
                    float2 v = { rv[i][hh] * v0, rv[i][hh] * v1 };
                    *(float2*)(C + off) = v;
                }
            }
        }
    }

    if (MODE == OUT_EXP) {
        #pragma unroll
        for (int i = 0; i < 2; i++)
            #pragma unroll
            for (int hh = 0; hh < 2; hh++) {
                rowacc[i][hh] += __shfl_xor_sync(0xffffffffu, rowacc[i][hh], 1);
                rowacc[i][hh] += __shfl_xor_sync(0xffffffffu, rowacc[i][hh], 2);
            }
        if ((lane & 3) == 0) {
            #pragma unroll
            for (int i = 0; i < 2; i++)
                #pragma unroll
                for (int hh = 0; hh < 2; hh++)
                    ssum[wm + i * 16 + hh * 8 + (lane >> 2)][warp >> 2] = rowacc[i][hh];
        }
        __syncthreads();
        if (tid < 128) {
            float sp = ssum[tid][0] + ssum[tid][1];
            Part[((long long)bz * NTOK + m0 + tid) * NTILES + blockIdx.x] = sp;
        }
    }
}

// ---------------- rowsum -> reciprocal ---------------------------------------
__global__ void rowsum_kernel(const float* __restrict__ part, float* __restrict__ rinv)
{
    int idx = blockIdx.x * 256 + threadIdx.x;
    const float* p = part + (long long)idx * NTILES;
    float s = 0.f;
    #pragma unroll
    for (int i = 0; i < NTILES; i++) s += p[i];
    rinv[idx] = 1.0f / s;
}

// ---------------- LayerNorm (+fp16 quantize) ---------------------------------
__global__ void ln_kernel(const float* __restrict__ x,
                          const float* __restrict__ gamma,
                          float* __restrict__ xn,
                          __half* __restrict__ xnh)
{
    int row = blockIdx.x;
    int t   = threadIdx.x;
    float v = x[row * DIM + t];

    __shared__ float s1[8], s2[8];
    float a = v, b = v * v;
    #pragma unroll
    for (int o = 16; o > 0; o >>= 1) {
        a += __shfl_xor_sync(0xffffffffu, a, o);
        b += __shfl_xor_sync(0xffffffffu, b, o);
    }
    int lane = t & 31, w = t >> 5;
    if (lane == 0) { s1[w] = a; s2[w] = b; }
    __syncthreads();
    if (t == 0) {
        float sa = 0.f, sb = 0.f;
        #pragma unroll
        for (int i = 0; i < 8; i++) { sa += s1[i]; sb += s2[i]; }
        s1[0] = sa * (1.0f / DIM);
        s2[0] = sb * (1.0f / DIM);
    }
    __syncthreads();
    float mu  = s1[0];
    float var = s2[0] - mu * mu;
    float rr  = rsqrtf(var + LN_EPS);
    float o = (v - mu) * rr * (gamma[t] + 1.0f);
    xn [row * DIM + t] = o;
    xnh[row * DIM + t] = __float2half(o);
}

// ---------------- combined split-K 64x64 precompute GEMM --------------------
// z in [0, HEADS*NSPLIT)          : Mt partial = Wk_h^T * Wq_h     (TN)
// z in [HEADS*NSPLIT, 2*H*NSPLIT) : G  partial = Wo_h  * Wv_h      (NN)
__global__ void __launch_bounds__(256)
gemm64_pre(const float* __restrict__ Wk, const float* __restrict__ Wq,
           const float* __restrict__ Wo, const float* __restrict__ Wv,
           float* __restrict__ pm, float* __restrict__ pg)
{
    __shared__ float As[16][68];
    __shared__ float Bs[16][68];

    int z = blockIdx.z;
    bool isG = z >= HEADS * NSPLIT;
    int zz = isG ? z - HEADS * NSPLIT : z;
    int h = zz / NSPLIT, sp = zz % NSPLIT;
    long long hk0 = (long long)h * DHEAD + (long long)sp * KS;

    const float* Ab = isG ? (Wo + hk0) : (Wk + hk0 * DIM);
    const float* Bb = (isG ? Wv : Wq) + hk0 * DIM;
    int lda = isG ? INNER : DIM;
    float* Cb = (isG ? pg : pm) + (long long)zz * DIM * DIM;

    int m0 = blockIdx.y * 64;
    int n0 = blockIdx.x * 64;
    int tid = threadIdx.x;
    int tx = tid & 15;
    int ty = tid >> 4;

    float acc[4][4];
    #pragma unroll
    for (int i = 0; i < 4; i++)
        #pragma unroll
        for (int j = 0; j < 4; j++) acc[i][j] = 0.f;

    for (int k0 = 0; k0 < KS; k0 += 16) {
        if (!isG) {
            int kk  = tid >> 4;
            int mm4 = (tid & 15) << 2;
            float4 a = *(const float4*)(Ab + (long long)(k0 + kk) * lda + m0 + mm4);
            *(float4*)&As[kk][mm4] = a;
        } else {
            int mm = tid >> 2;
            int kq = (tid & 3) << 2;
            float4 a = *(const float4*)(Ab + (long long)(m0 + mm) * lda + k0 + kq);
            As[kq + 0][mm] = a.x;
            As[kq + 1][mm] = a.y;
            As[kq + 2][mm] = a.z;
            As[kq + 3][mm] = a.w;
        }
        {
            int kk  = tid >> 4;
            int nn4 = (tid & 15) << 2;
            float4 b = *(const float4*)(Bb + (long long)(k0 + kk) * DIM + n0 + nn4);
            *(float4*)&Bs[kk][nn4] = b;
        }
        __syncthreads();

        #pragma unroll
        for (int kk = 0; kk < 16; kk++) {
            float4 ra = *(const float4*)&As[kk][ty * 4];
            float4 rb = *(const float4*)&Bs[kk][tx * 4];
            float va[4] = { ra.x, ra.y, ra.z, ra.w };
            float vb[4] = { rb.x, rb.y, rb.z, rb.w };
            #pragma unroll
            for (int i = 0; i < 4; i++)
                #pragma unroll
                for (int j = 0; j < 4; j++)
                    acc[i][j] = fmaf(va[i], vb[j], acc[i][j]);
        }
        __syncthreads();
    }

    #pragma unroll
    for (int i = 0; i < 4; i++)
        #pragma unroll
        for (int j = 0; j < 4; j++)
            Cb[(long long)(m0 + ty * 4 + i) * DIM + (n0 + tx * 4 + j)] = acc[i][j];
}

// ------------- reduce split-K partials (both Mt and G) -> fp16 --------------
__global__ void reduce_pre_kernel(const float* __restrict__ pm,
                                  const float* __restrict__ pg,
                                  __half* __restrict__ mth,
                                  __half* __restrict__ ghh)
{
    int gi = blockIdx.x * 256 + threadIdx.x;          // over 2*HEADS*DIM*DIM
    bool isG = gi >= HEADS * DIM * DIM;
    int idx = isG ? gi - HEADS * DIM * DIM : gi;
    int h   = idx >> 16;
    int off = idx & 65535;
    const float* p = (isG ? pg : pm) + (long long)h * NSPLIT * 65536 + off;
    float acc = 0.f;
    #pragma unroll
    for (int s = 0; s < NSPLIT; s++) acc += p[(long long)s * 65536];
    (isG ? ghh : mth)[idx] = __float2half(acc);
}

// ---------------- reduce per-head partials ----------------------------------
__global__ void reduce_kernel(const float* __restrict__ op, float* __restrict__ out)
{
    int row = blockIdx.x;
    int t   = threadIdx.x;
    int b   = row >> 11;
    int q   = row & 2047;
    const float* base = op + (((long long)b * HEADS) * NTOK + q) * DIM + t;
    float acc = 0.f;
    #pragma unroll
    for (int h = 0; h < HEADS; h++)
        acc += base[(long long)h * NTOK * DIM];
    out[(long long)row * DIM + t] = acc;
}

// ---------------- launch ----------------------------------------------------
extern "C" void kernel_launch(void* const* d_in, const int* in_sizes, int n_in,
                              void* d_out, int out_size)
{
    const float* x     = (const float*)d_in[0];
    const float* gamma = (const float*)d_in[1];
    const float* Wq    = (const float*)d_in[2];
    const float* Wk    = (const float*)d_in[3];
    const float* Wv    = (const float*)d_in[4];
    const float* Wo    = (const float*)d_in[5];
    float* out = (float*)d_out;

    cudaFuncSetAttribute(mma_nt<OUT_F32>, cudaFuncAttributeMaxDynamicSharedMemorySize, MM_SMEM);
    cudaFuncSetAttribute(mma_nt<OUT_F16>, cudaFuncAttributeMaxDynamicSharedMemorySize, MM_SMEM);
    cudaFuncSetAttribute(mma_nt<OUT_EXP>, cudaFuncAttributeMaxDynamicSharedMemorySize, MM_SMEM);
    cudaFuncSetAttribute(mma_nt<OUT_DIV>, cudaFuncAttributeMaxDynamicSharedMemorySize, MM_SMEM);

    float *xn, *pm, *pg, *op, *sp, *ri;
    __half *xnh, *mth, *ghh, *th, *uth, *eh;
    cudaGetSymbolAddress((void**)&xn,  g_xn);
    cudaGetSymbolAddress((void**)&pm,  g_pm);
    cudaGetSymbolAddress((void**)&pg,  g_pg);
    cudaGetSymbolAddress((void**)&op,  g_op);
    cudaGetSymbolAddress((void**)&sp,  g_sp);
    cudaGetSymbolAddress((void**)&ri,  g_ri);
    cudaGetSymbolAddress((void**)&xnh, g_xnh);
    cudaGetSymbolAddress((void**)&mth, g_mth);
    cudaGetSymbolAddress((void**)&ghh, g_ghh);
    cudaGetSymbolAddress((void**)&th,  g_th);
    cudaGetSymbolAddress((void**)&uth, g_uth);
    cudaGetSymbolAddress((void**)&eh,  g_eh);

    const long long TD  = (long long)NTOK * DIM;
    const long long HTD = (long long)HEADS * TD;
    const long long SB  = (long long)NTOK * INNER;
    const long long DD  = (long long)DIM * DIM;

    // 1) LayerNorm (+fp16 quantize fused)
    ln_kernel<<<TOK, 256>>>(x, gamma, xn, xnh);

    // 2) combined precomputes: Mt_h = Wk_h^T Wq_h ; G_h = Wo_h Wv_h
    {
        dim3 grid(4, 4, 2 * HEADS * NSPLIT);
        gemm64_pre<<<grid, 256>>>(Wk, Wq, Wo, Wv, pm, pg);
        reduce_pre_kernel<<<2 * HEADS * DIM * DIM / 256, 256>>>(pm, pg, mth, ghh);
    }

    // 3) T[b][h] = xn_b * Mt_h^T
    {
        dim3 grid(DIM / 64, NTOK / 128, BATCH * HEADS);
        mma_nt<OUT_F16><<<grid, 256, MM_SMEM>>>(
            xnh, mth, nullptr, th, nullptr, nullptr,
            DIM, DIM, DIM, DIM, HEADS,
            TD, 0, 0, DD, HTD, TD, 1.0f);
    }

    // 4) E = exp(scale * T * xn^T)  (+ row-sum partials)
    {
        dim3 grid(NTOK / 64, NTOK / 128, BATCH * HEADS);
        mma_nt<OUT_EXP><<<grid, 256, MM_SMEM>>>(
            th, xnh, nullptr, eh, sp, nullptr,
            DIM, DIM, DIM, INNER, HEADS,
            HTD, TD, TD, 0, SB, (long long)DHEAD,
            ATT_SCALE);
    }

    // 5) rinv = 1 / rowsum
    rowsum_kernel<<<NROWS / 256, 256>>>(sp, ri);

    // 6) Ut[b][h] = G_h * xn_b^T
    {
        dim3 grid(NTOK / 64, DIM / 128, BATCH * HEADS);
        mma_nt<OUT_F16><<<grid, 256, MM_SMEM>>>(
            ghh, xnh, nullptr, uth, nullptr, nullptr,
            DIM, DIM, DIM, NTOK, HEADS,
            0, DD, TD, 0, HTD, TD, 1.0f);
    }

    // 7) op[b][h] = (E[b][h] * Ut[b][h]^T) * rinv
    {
        dim3 grid(DIM / 64, NTOK / 128, BATCH * HEADS);
        mma_nt<OUT_DIV><<<grid, 256, MM_SMEM>>>(
            eh, uth, op, nullptr, nullptr, ri,
            NTOK, INNER, NTOK, DIM, HEADS,
            SB, (long long)DHEAD, HTD, TD, HTD, TD,
            1.0f);
    }

    // 8) out = sum_h op[b][h]
    reduce_kernel<<<TOK, 256>>>(op, out);
}